// round 4
// baseline (speedup 1.0000x reference)
#include <cuda_runtime.h>
#include <math.h>

#define MM 256
#define DD 768
#define THRESH 0.3f
#define EPSF 1e-8f

// ---------------- device scratch (no allocations allowed) ----------------
__device__ float g_nm2[MM];          // ||m_i||^2
__device__ float g_rnm[MM];          // 1/max(||m_i||, EPS)
__device__ float g_Sm[MM];           // sum(m_i)
__device__ float g_kx[MM];           // dot(m_i, x)
__device__ float g_mask[MM];
__device__ float g_nx, g_Sx, g_cnt, g_A2;
__device__ float g_km[MM * MM];      // mem @ mem^T
__device__ float g_A1[MM];
__device__ unsigned g_ctr;           // zero-initialized; reset by epilogue each run

// ---------------- K_prep: gram + stats + (last-block) mask/cnt/A2/A1 -------
// grid = 513 blocks of 256 threads.
//   blocks [0,256):    16x16 gram tiles of mem @ mem^T
//   blocks [256,512):  per-row stats (||m||^2, sum, dot with x)
//   block  512:        x stats (||x||, sum)
// The last block to arrive (atomic counter) runs the epilogue: mask, cnt,
// A2, and A1[i] = sum_j km[j,i] * mask[j]/||m_j||  (gram is symmetric, so
// the column read is coalesced). It then resets the counter (replay-safe).
__global__ void k_prep(const float* __restrict__ x, const float* __restrict__ mem) {
    __shared__ float sA[16][65];
    __shared__ float sB[16][65];
    __shared__ float red[3][8];
    __shared__ float sh_w[MM];
    __shared__ bool s_last;

    int b = blockIdx.x, t = threadIdx.x;

    if (b < 256) {
        // ---- gram tile ----
        int ty = t >> 4, tx = t & 15;
        int r0 = (b >> 4) * 16, c0 = (b & 15) * 16;
        float acc = 0.f;
        for (int k0 = 0; k0 < DD; k0 += 64) {
#pragma unroll
            for (int q = 0; q < 4; q++) {
                int idx = t + q * 256;
                int rr = idx >> 6, cc = idx & 63;
                sA[rr][cc] = mem[(r0 + rr) * DD + k0 + cc];
                sB[rr][cc] = mem[(c0 + rr) * DD + k0 + cc];
            }
            __syncthreads();
#pragma unroll
            for (int k = 0; k < 64; k++)
                acc = fmaf(sA[ty][k], sB[tx][k], acc);
            __syncthreads();
        }
        g_km[(r0 + ty) * MM + (c0 + tx)] = acc;
    } else {
        // ---- row / x stats ----
        int r = b - 256;
        float s0 = 0.f, s1 = 0.f, s2 = 0.f;
        if (r < MM) {
            const float* row = mem + r * DD;
            for (int d = t; d < DD; d += 256) {
                float v = row[d], xv = x[d];
                s0 = fmaf(v, v, s0);
                s1 += v;
                s2 = fmaf(v, xv, s2);
            }
        } else {
            for (int d = t; d < DD; d += 256) {
                float xv = x[d];
                s0 = fmaf(xv, xv, s0);
                s1 += xv;
            }
        }
#pragma unroll
        for (int o = 16; o; o >>= 1) {
            s0 += __shfl_down_sync(0xffffffffu, s0, o);
            s1 += __shfl_down_sync(0xffffffffu, s1, o);
            s2 += __shfl_down_sync(0xffffffffu, s2, o);
        }
        if ((t & 31) == 0) { int w = t >> 5; red[0][w] = s0; red[1][w] = s1; red[2][w] = s2; }
        __syncthreads();
        if (t == 0) {
            float a = 0.f, c = 0.f, e = 0.f;
            for (int w = 0; w < 8; w++) { a += red[0][w]; c += red[1][w]; e += red[2][w]; }
            if (r < MM) {
                g_nm2[r] = a;
                g_rnm[r] = 1.f / fmaxf(sqrtf(a), EPSF);
                g_Sm[r] = c;
                g_kx[r] = e;
            } else {
                g_nx = fmaxf(sqrtf(a), EPSF);
                g_Sx = c;
            }
        }
    }

    // ---- arrival + last-block epilogue ----
    __threadfence();
    __syncthreads();
    if (t == 0) {
        unsigned old = atomicAdd(&g_ctr, 1u);
        s_last = (old == 512u);
    }
    __syncthreads();
    if (!s_last) return;
    __threadfence();

    // mask, w, and cnt/A2 partials (t indexes memory row)
    float rnmt = g_rnm[t];
    float mx = g_kx[t] * rnmt / g_nx;
    float mk = (mx > THRESH) ? 1.f : 0.f;
    g_mask[t] = mk;
    float w = mk * rnmt;
    sh_w[t] = w;

    float c0v = mk;
    float c1v = mk * g_Sm[t] * rnmt;
#pragma unroll
    for (int o = 16; o; o >>= 1) {
        c0v += __shfl_down_sync(0xffffffffu, c0v, o);
        c1v += __shfl_down_sync(0xffffffffu, c1v, o);
    }
    if ((t & 31) == 0) { int wi = t >> 5; red[0][wi] = c0v; red[1][wi] = c1v; }
    __syncthreads();
    if (t == 0) {
        float a = 0.f, bb = 0.f;
        for (int wi = 0; wi < 8; wi++) { a += red[0][wi]; bb += red[1][wi]; }
        g_cnt = a;
        g_A2 = bb;
    }

    // A1[t] = sum_j km[j,t] * w[j]   (coalesced column reads; km symmetric)
    float acc = 0.f;
#pragma unroll 8
    for (int j = 0; j < MM; j++)
        acc = fmaf(g_km[j * MM + t], sh_w[j], acc);
    g_A1[t] = acc;

    if (t == 0) g_ctr = 0u;   // reset for next graph replay
}

// ---------------- K_out: inline-s + streaming broadcast-add ----------------
// grid (i=256, a-chunk=8), 192 threads; thread owns one float4 of the D row.
// Threads 0..31 compute the 32 per-(a,i) scalars into shared first.
__global__ void k_out(const float4* __restrict__ memv,
                      const float4* __restrict__ noise,
                      float4* __restrict__ out) {
    __shared__ float s_sh[32];
    __shared__ float m_sh[32];
    int i = blockIdx.x;
    int a0 = blockIdx.y << 5;
    int t = threadIdx.x;

    float4 mv = memv[i * 192 + t];

    if (t < 32) {
        int a = a0 + t;
        float mk = g_mask[a];
        m_sh[t] = mk;
        float rnmi = g_rnm[i];
        float nx = g_nx;
        float kxi = g_kx[i];
        // c[a,i] = km_cos[i,a] + mx_cos[i]
        float c = g_km[i * MM + a] * rnmi * g_rnm[a] + kxi * rnmi / nx;
        float nkp = sqrtf(fmaxf(g_nm2[i] + 2.f * c * g_Sm[i] + (float)DD * c * c,
                                EPSF * EPSF));
        float ckx = (kxi + c * g_Sx) / (nkp * nx);
        float cnt = g_cnt;
        float mean = (cnt > 0.f) ? (g_A1[i] + c * g_A2) / (nkp * fmaxf(cnt, 1.f))
                                 : 0.f;
        s_sh[t] = c + ckx + mean;
    }
    __syncthreads();

#pragma unroll 4
    for (int q = 0; q < 32; q++) {
        int a = a0 + q;
        int base = (a * MM + i) * 192 + t;   // max ~12.6M float4 < 2^31
        if (m_sh[q] != 0.f) {
            float s = s_sh[q];
            float4 nz = noise[base];
            float4 r;
            r.x = mv.x + s + nz.x;
            r.y = mv.y + s + nz.y;
            r.z = mv.z + s + nz.z;
            r.w = mv.w + s + nz.w;
            out[base] = r;
        } else {
            out[base] = make_float4(0.f, 0.f, 0.f, 0.f);
        }
    }
}

// ---------------- launch ----------------
extern "C" void kernel_launch(void* const* d_in, const int* in_sizes, int n_in,
                              void* d_out, int out_size) {
    const float* x     = (const float*)d_in[0];
    const float* mem   = (const float*)d_in[1];
    const float* noise = (const float*)d_in[2];
    float* out = (float*)d_out;

    k_prep<<<513, 256>>>(x, mem);
    k_out<<<dim3(MM, 8), 192>>>((const float4*)mem, (const float4*)noise,
                                (float4*)out);
}

// round 6
// speedup vs baseline: 1.2118x; 1.2118x over previous
#include <cuda_runtime.h>
#include <math.h>

#define MM 256
#define DD 768
#define THRESH 0.3f
#define EPSF 1e-8f

// ---------------- device scratch (no allocations allowed) ----------------
__device__ float g_nm2[MM];          // ||m_i||^2
__device__ float g_rnm[MM];          // 1/max(||m_i||, EPS)
__device__ float g_Sm[MM];           // sum(m_i)
__device__ float g_kx[MM];           // dot(m_i, x)
__device__ float g_mask[MM];
__device__ float g_w[MM];            // mask * rnm
__device__ float g_nx, g_Sx, g_cnt, g_A2;
__device__ float g_km[MM * MM];      // mem @ mem^T
__device__ float g_sT[MM * MM];      // s transposed: g_sT[i*MM + a]

// ---------------- K1: per-row stats + x stats (257 blocks) ----------------
__global__ void k_stats(const float* __restrict__ x, const float* __restrict__ mem) {
    int b = blockIdx.x, t = threadIdx.x;
    float s0 = 0.f, s1 = 0.f, s2 = 0.f;
    if (b < MM) {
        const float* row = mem + b * DD;
        for (int d = t; d < DD; d += 256) {
            float v = row[d], xv = x[d];
            s0 = fmaf(v, v, s0);
            s1 += v;
            s2 = fmaf(v, xv, s2);
        }
    } else {
        for (int d = t; d < DD; d += 256) {
            float xv = x[d];
            s0 = fmaf(xv, xv, s0);
            s1 += xv;
        }
    }
    __shared__ float sh[3][8];
#pragma unroll
    for (int o = 16; o; o >>= 1) {
        s0 += __shfl_down_sync(0xffffffffu, s0, o);
        s1 += __shfl_down_sync(0xffffffffu, s1, o);
        s2 += __shfl_down_sync(0xffffffffu, s2, o);
    }
    if ((t & 31) == 0) { int w = t >> 5; sh[0][w] = s0; sh[1][w] = s1; sh[2][w] = s2; }
    __syncthreads();
    if (t == 0) {
        float a = 0.f, c = 0.f, e = 0.f;
        for (int w = 0; w < 8; w++) { a += sh[0][w]; c += sh[1][w]; e += sh[2][w]; }
        if (b < MM) {
            g_nm2[b] = a;
            g_rnm[b] = 1.f / fmaxf(sqrtf(a), EPSF);
            g_Sm[b] = c;
            g_kx[b] = e;
        } else {
            g_nx = fmaxf(sqrtf(a), EPSF);
            g_Sx = c;
        }
    }
}

// ---------------- K2: gram tiles; block 0 also does mask/cnt/A2/w ----------
// 256 blocks of 256 threads; block b -> 16x16 output tile.
__global__ void k_gram(const float* __restrict__ mem) {
    __shared__ float sA[16][65];
    __shared__ float sB[16][65];
    int t = threadIdx.x;
    int ty = t >> 4, tx = t & 15;
    int r0 = (blockIdx.x >> 4) * 16, c0 = (blockIdx.x & 15) * 16;
    float acc = 0.f;
    for (int k0 = 0; k0 < DD; k0 += 64) {
#pragma unroll
        for (int q = 0; q < 4; q++) {
            int idx = t + q * 256;
            int rr = idx >> 6, cc = idx & 63;
            sA[rr][cc] = mem[(r0 + rr) * DD + k0 + cc];
            sB[rr][cc] = mem[(c0 + rr) * DD + k0 + cc];
        }
        __syncthreads();
#pragma unroll
        for (int k = 0; k < 64; k++)
            acc = fmaf(sA[ty][k], sB[tx][k], acc);
        __syncthreads();
    }
    g_km[(r0 + ty) * MM + (c0 + tx)] = acc;

    // block 0: mask / cnt / A2 / w (reads only K1 outputs -> kernel-boundary safe)
    if (blockIdx.x == 0) {
        float rnmt = g_rnm[t];
        float mx = g_kx[t] * rnmt / g_nx;
        float mk = (mx > THRESH) ? 1.f : 0.f;
        g_mask[t] = mk;
        g_w[t] = mk * rnmt;
        float c0v = mk;
        float c1v = mk * g_Sm[t] * rnmt;
        __shared__ float red[2][8];
#pragma unroll
        for (int o = 16; o; o >>= 1) {
            c0v += __shfl_down_sync(0xffffffffu, c0v, o);
            c1v += __shfl_down_sync(0xffffffffu, c1v, o);
        }
        if ((t & 31) == 0) { int w = t >> 5; red[0][w] = c0v; red[1][w] = c1v; }
        __syncthreads();
        if (t == 0) {
            float a = 0.f, bb = 0.f;
            for (int w = 0; w < 8; w++) { a += red[0][w]; bb += red[1][w]; }
            g_cnt = a;
            g_A2 = bb;
        }
    }
}

// ---------------- K3: block i -> A1[i] + s[:, i] (transposed store) --------
__global__ void k_s(void) {
    __shared__ float red[8];
    __shared__ float sh_A1;
    int i = blockIdx.x, t = threadIdx.x;

    float kmv = g_km[i * MM + t];        // km[i, t], coalesced; symmetric

    // A1[i] = sum_j km[i,j] * w[j]
    float v = kmv * g_w[t];
#pragma unroll
    for (int o = 16; o; o >>= 1) v += __shfl_down_sync(0xffffffffu, v, o);
    if ((t & 31) == 0) red[t >> 5] = v;
    __syncthreads();
    if (t == 0) {
        float s = 0.f;
        for (int w = 0; w < 8; w++) s += red[w];
        sh_A1 = s;
    }
    __syncthreads();

    // per-a scalar, a = t
    float rnmi = g_rnm[i];
    float nx = g_nx;
    float kxi = g_kx[i];
    float c = kmv * rnmi * g_rnm[t] + kxi * rnmi / nx;
    float nkp = sqrtf(fmaxf(g_nm2[i] + 2.f * c * g_Sm[i] + (float)DD * c * c,
                            EPSF * EPSF));
    float ckx = (kxi + c * g_Sx) / (nkp * nx);
    float cnt = g_cnt;
    float mean = (cnt > 0.f) ? (sh_A1 + c * g_A2) / (nkp * fmaxf(cnt, 1.f)) : 0.f;
    g_sT[i * MM + t] = c + ckx + mean;   // coalesced
}

// ---------------- K4: streaming broadcast-add (HBM-bound) ------------------
// grid (i=256, a-chunk=8), 192 threads; thread owns one float4 of the D row.
__global__ void k_out(const float4* __restrict__ memv,
                      const float4* __restrict__ noise,
                      float4* __restrict__ out) {
    __shared__ float s_sh[32];
    __shared__ float m_sh[32];
    int i = blockIdx.x;
    int a0 = blockIdx.y << 5;
    int t = threadIdx.x;

    float4 mv = memv[i * 192 + t];

    if (t < 32) {
        m_sh[t] = g_mask[a0 + t];
        s_sh[t] = g_sT[i * MM + a0 + t];   // one 128B line
    }
    __syncthreads();

#pragma unroll 4
    for (int q = 0; q < 32; q++) {
        int a = a0 + q;
        int base = (a * MM + i) * 192 + t;   // < 2^31
        if (m_sh[q] != 0.f) {
            float s = s_sh[q];
            float4 nz = __ldcs(&noise[base]);    // evict-first: read-once
            float4 r;
            r.x = mv.x + s + nz.x;
            r.y = mv.y + s + nz.y;
            r.z = mv.z + s + nz.z;
            r.w = mv.w + s + nz.w;
            __stcs(&out[base], r);               // streaming store
        } else {
            __stcs(&out[base], make_float4(0.f, 0.f, 0.f, 0.f));
        }
    }
}

// ---------------- launch ----------------
extern "C" void kernel_launch(void* const* d_in, const int* in_sizes, int n_in,
                              void* d_out, int out_size) {
    const float* x     = (const float*)d_in[0];
    const float* mem   = (const float*)d_in[1];
    const float* noise = (const float*)d_in[2];
    float* out = (float*)d_out;

    k_stats<<<MM + 1, 256>>>(x, mem);
    k_gram<<<256, 256>>>(mem);
    k_s<<<MM, 256>>>();
    k_out<<<dim3(MM, 8), 192>>>((const float4*)mem, (const float4*)noise,
                                (float4*)out);
}